// round 8
// baseline (speedup 1.0000x reference)
#include <cuda_runtime.h>
#include <cuda_bf16.h>

// Problem constants (FullAttention_73650099192077)
#define B_SZ 4
#define L_Q  2048
#define S_K  2048
#define H_N  8
#define E_N  64
#define D_N  64

#define BM 128             // query rows per CTA (8 warps x 16)
#define BN 64              // keys per tile
#define NT 256
#define NTILES (S_K / BN)

#define TOT (B_SZ * H_N * 2048 * 64)

// Preprocessed split-bf16 tensors, layout [b*H+h][s][e] (rows of 64 bf16 = 128 B)
__device__ __nv_bfloat16 g_qh[TOT];   // Q hi (pre-scaled by 0.125*log2e)
__device__ __nv_bfloat16 g_ql[TOT];
__device__ __nv_bfloat16 g_kh[TOT];
__device__ __nv_bfloat16 g_kl[TOT];
__device__ __nv_bfloat16 g_vh[TOT];
__device__ __nv_bfloat16 g_vl[TOT];

// ---- smem: double buffer x {KH, KL, VH, VL} of 64x64 bf16 (8 KB each) ----
#define SMB_KH 0
#define SMB_KL 8192
#define SMB_VH 16384
#define SMB_VL 24576
#define BUFSZ  32768
#define SM_TOTAL (2 * BUFSZ)    // 64 KB

// =================== helpers ===================
static __device__ __forceinline__ unsigned smem_u32(const void* p) {
    unsigned a;
    asm("{ .reg .u64 t; cvta.to.shared.u64 t, %1; cvt.u32.u64 %0, t; }" : "=r"(a) : "l"(p));
    return a;
}
static __device__ __forceinline__ unsigned swz(unsigned base, int row, int bytecol) {
    return base + (unsigned)(row * 128) + (unsigned)(bytecol ^ ((row & 7) << 4));
}
static __device__ __forceinline__ void ldsm_x4(unsigned* r, unsigned addr) {
    asm volatile("ldmatrix.sync.aligned.m8n8.x4.shared.b16 {%0,%1,%2,%3}, [%4];"
                 : "=r"(r[0]), "=r"(r[1]), "=r"(r[2]), "=r"(r[3]) : "r"(addr));
}
static __device__ __forceinline__ void ldsm_x4_t(unsigned* r, unsigned addr) {
    asm volatile("ldmatrix.sync.aligned.m8n8.x4.trans.shared.b16 {%0,%1,%2,%3}, [%4];"
                 : "=r"(r[0]), "=r"(r[1]), "=r"(r[2]), "=r"(r[3]) : "r"(addr));
}
static __device__ __forceinline__ void mma16816(float* c, const unsigned* a, unsigned b0, unsigned b1) {
    asm volatile("mma.sync.aligned.m16n8k16.row.col.f32.bf16.bf16.f32 "
                 "{%0,%1,%2,%3}, {%4,%5,%6,%7}, {%8,%9}, {%0,%1,%2,%3};"
                 : "+f"(c[0]), "+f"(c[1]), "+f"(c[2]), "+f"(c[3])
                 : "r"(a[0]), "r"(a[1]), "r"(a[2]), "r"(a[3]), "r"(b0), "r"(b1));
}
static __device__ __forceinline__ void split2(float x, float y, unsigned& h, unsigned& l) {
    __nv_bfloat162 hb = __floats2bfloat162_rn(x, y);
    float hx = __low2float(hb), hy = __high2float(hb);
    __nv_bfloat162 lb = __floats2bfloat162_rn(x - hx, y - hy);
    h = *reinterpret_cast<unsigned*>(&hb);
    l = *reinterpret_cast<unsigned*>(&lb);
}
static __device__ __forceinline__ void cpa16(unsigned saddr, const void* gp) {
    asm volatile("cp.async.cg.shared.global [%0], [%1], 16;" :: "r"(saddr), "l"(gp));
}
#define CP_COMMIT() asm volatile("cp.async.commit_group;" ::: "memory")
#define CP_WAIT(n)  asm volatile("cp.async.wait_group %0;" :: "n"(n) : "memory")

// =================== preprocess: fp32 [b,s,h,e] -> split bf16 [b*H+h][s][e] ===================
__global__ void prep_kernel(const float* __restrict__ src,
                            __nv_bfloat16* __restrict__ dh,
                            __nv_bfloat16* __restrict__ dl,
                            float scale)
{
    int idx = blockIdx.x * blockDim.x + threadIdx.x;
    int e4 = idx & 15;
    int h  = (idx >> 4) & (H_N - 1);
    int s  = (idx >> 7) & 2047;
    int b  = idx >> 18;
    float4 v = *reinterpret_cast<const float4*>(src + (size_t)idx * 4);
    unsigned h0, l0, h1, l1;
    split2(v.x * scale, v.y * scale, h0, l0);
    split2(v.z * scale, v.w * scale, h1, l1);
    size_t doff = ((((size_t)b * H_N + h) * 2048 + s) * 64 + e4 * 4);
    *reinterpret_cast<uint2*>(dh + doff) = make_uint2(h0, h1);
    *reinterpret_cast<uint2*>(dl + doff) = make_uint2(l0, l1);
}

// =================== main kernel ===================
__global__ __launch_bounds__(NT, 1)
void fullattn_hmma4_kernel(float* __restrict__ O)
{
    extern __shared__ __align__(128) char smbuf[];
    const unsigned sb = smem_u32(smbuf);

    const int t    = threadIdx.x;
    const int wid  = t >> 5;
    const int lane = t & 31;
    const int g    = lane >> 2;
    const int tg   = lane & 3;
    const int l0   = blockIdx.x * BM;
    const int bh   = blockIdx.y;
    const int b    = bh >> 3;
    const int h    = bh & 7;

    const size_t gbase = (size_t)bh * S_K * 64;

    // ---- Q (pre-scaled/split): cp.async stage 128x64 hi + lo, ldmatrix to A-frags ----
    {
        const int r  = t >> 1;
        const int hf = t & 1;
        const size_t qoff = ((size_t)bh * L_Q + l0 + r) * 64 + hf * 32;
        #pragma unroll
        for (int c = 0; c < 4; c++) {
            const unsigned soff = hf * 64 + c * 16;
            cpa16(swz(sb, r, soff),         g_qh + qoff + c * 8);
            cpa16(swz(sb + 16384, r, soff), g_ql + qoff + c * 8);
        }
        CP_COMMIT();
        CP_WAIT(0);
        __syncthreads();
    }
    unsigned qh[16], ql[16];
    #pragma unroll
    for (int kb = 0; kb < 4; kb++) {
        const unsigned la = swz(sb, wid * 16 + (lane & 15), kb * 32 + (lane >> 4) * 16);
        ldsm_x4(&qh[kb * 4], la);
        ldsm_x4(&ql[kb * 4], la + 16384);
    }
    __syncthreads();

    // ---- K/V tile loader: each thread fills one 128B row of one array ----
    const int lrow  = t & 63;
    const int lpart = t >> 6;    // 0..3 -> KH, KL, VH, VL
    const __nv_bfloat16* lsrc =
        (lpart == 0) ? g_kh : (lpart == 1) ? g_kl : (lpart == 2) ? g_vh : g_vl;
    auto load_tile = [&](int tile, int bufsel) {
        const unsigned bb = sb + bufsel * BUFSZ + lpart * 8192;
        const size_t off = gbase + ((size_t)(tile * BN + lrow)) * 64;
        #pragma unroll
        for (int c = 0; c < 8; c++)
            cpa16(swz(bb, lrow, c * 16), lsrc + off + c * 8);
        CP_COMMIT();
    };

    // ---- QK^T GEMM for one tile buffer into acc ----
    auto qk_gemm = [&](unsigned bb, float (*acc)[4]) {
        #pragma unroll
        for (int j = 0; j < 8; j++)
            #pragma unroll
            for (int i = 0; i < 4; i++) acc[j][i] = 0.0f;
        #pragma unroll
        for (int jj = 0; jj < 4; jj++) {
            #pragma unroll
            for (int kb = 0; kb < 4; kb++) {
                const unsigned la = swz(bb, 16 * jj + (lane & 15), kb * 32 + (lane >> 4) * 16);
                unsigned bh4[4], bl4[4];
                ldsm_x4(bh4, la + SMB_KH);
                ldsm_x4(bl4, la + SMB_KL);
                mma16816(acc[2 * jj],     &qh[kb * 4], bh4[0], bh4[2]);
                mma16816(acc[2 * jj],     &qh[kb * 4], bl4[0], bl4[2]);
                mma16816(acc[2 * jj],     &ql[kb * 4], bh4[0], bh4[2]);
                mma16816(acc[2 * jj + 1], &qh[kb * 4], bh4[1], bh4[3]);
                mma16816(acc[2 * jj + 1], &qh[kb * 4], bl4[1], bl4[3]);
                mma16816(acc[2 * jj + 1], &ql[kb * 4], bh4[1], bh4[3]);
            }
        }
    };

    load_tile(0, 0);
    load_tile(1, 1);

    float o[8][4];
    #pragma unroll
    for (int j = 0; j < 8; j++)
        #pragma unroll
        for (int i = 0; i < 4; i++) o[j][i] = 0.0f;
    float m0 = -1e30f, m1 = -1e30f;
    float l0s = 0.0f, l1s = 0.0f;

    CP_WAIT(1);
    __syncthreads();

    float scur[8][4], snxt[8][4];
    qk_gemm(sb, scur);   // tile 0 in buffer 0

    for (int tile = 0; tile < NTILES; tile++) {
        const unsigned bcur = sb + (tile & 1) * BUFSZ;
        const unsigned bnxt = sb + ((tile + 1) & 1) * BUFSZ;

        // ---- QK for NEXT tile first (independent of softmax below -> overlap) ----
        if (tile + 1 < NTILES) {
            CP_WAIT(0);            // tile t+1's group complete
            __syncthreads();
            qk_gemm(bnxt, snxt);
        }

        // ---- online softmax on scur (base-2; log2e folded into Q prescale) ----
        float mx0 = -1e30f, mx1 = -1e30f;
        #pragma unroll
        for (int j = 0; j < 8; j++) {
            mx0 = fmaxf(mx0, fmaxf(scur[j][0], scur[j][1]));
            mx1 = fmaxf(mx1, fmaxf(scur[j][2], scur[j][3]));
        }
        #pragma unroll
        for (int off = 1; off < 4; off <<= 1) {
            mx0 = fmaxf(mx0, __shfl_xor_sync(0xffffffffu, mx0, off));
            mx1 = fmaxf(mx1, __shfl_xor_sync(0xffffffffu, mx1, off));
        }
        const float nm0 = fmaxf(m0, mx0), nm1 = fmaxf(m1, mx1);
        const float a0 = exp2f(m0 - nm0), a1 = exp2f(m1 - nm1);
        m0 = nm0; m1 = nm1;

        float rs0 = 0.0f, rs1 = 0.0f;
        #pragma unroll
        for (int j = 0; j < 8; j++) {
            scur[j][0] = exp2f(scur[j][0] - nm0);
            scur[j][1] = exp2f(scur[j][1] - nm0);
            scur[j][2] = exp2f(scur[j][2] - nm1);
            scur[j][3] = exp2f(scur[j][3] - nm1);
            rs0 += scur[j][0] + scur[j][1];
            rs1 += scur[j][2] + scur[j][3];
        }
        #pragma unroll
        for (int off = 1; off < 4; off <<= 1) {
            rs0 += __shfl_xor_sync(0xffffffffu, rs0, off);
            rs1 += __shfl_xor_sync(0xffffffffu, rs1, off);
        }
        l0s = l0s * a0 + rs0;
        l1s = l1s * a1 + rs1;
        #pragma unroll
        for (int j = 0; j < 8; j++) {
            o[j][0] *= a0; o[j][1] *= a0;
            o[j][2] *= a1; o[j][3] *= a1;
        }

        // ---- pack P hi/lo into A-fragments (C->A identity) ----
        unsigned ph[16], pl[16];
        #pragma unroll
        for (int kb = 0; kb < 4; kb++) {
            split2(scur[2 * kb][0],     scur[2 * kb][1],     ph[kb * 4 + 0], pl[kb * 4 + 0]);
            split2(scur[2 * kb][2],     scur[2 * kb][3],     ph[kb * 4 + 1], pl[kb * 4 + 1]);
            split2(scur[2 * kb + 1][0], scur[2 * kb + 1][1], ph[kb * 4 + 2], pl[kb * 4 + 2]);
            split2(scur[2 * kb + 1][2], scur[2 * kb + 1][3], ph[kb * 4 + 3], pl[kb * 4 + 3]);
        }

        // ---- PV on current buffer (V via ldmatrix.trans) ----
        #pragma unroll
        for (int jj = 0; jj < 4; jj++) {
            #pragma unroll
            for (int kb = 0; kb < 4; kb++) {
                const unsigned la = swz(bcur, 16 * kb + (lane & 15), jj * 32 + (lane >> 4) * 16);
                unsigned vh4[4], vl4[4];
                ldsm_x4_t(vh4, la + SMB_VH);
                ldsm_x4_t(vl4, la + SMB_VL);
                mma16816(o[2 * jj],     &ph[kb * 4], vh4[0], vh4[1]);
                mma16816(o[2 * jj],     &ph[kb * 4], vl4[0], vl4[1]);
                mma16816(o[2 * jj],     &pl[kb * 4], vh4[0], vh4[1]);
                mma16816(o[2 * jj + 1], &ph[kb * 4], vh4[2], vh4[3]);
                mma16816(o[2 * jj + 1], &ph[kb * 4], vl4[2], vl4[3]);
                mma16816(o[2 * jj + 1], &pl[kb * 4], vh4[2], vh4[3]);
            }
        }

        __syncthreads();                 // buf[tile&1] fully consumed
        if (tile + 2 < NTILES) load_tile(tile + 2, tile & 1);

        // rotate accumulators
        #pragma unroll
        for (int j = 0; j < 8; j++)
            #pragma unroll
            for (int i = 0; i < 4; i++) scur[j][i] = snxt[j][i];
    }

    // ---- epilogue: normalize + store ----
    const float inv0 = 1.0f / l0s;
    const float inv1 = 1.0f / l1s;
    const int r0 = l0 + wid * 16 + g;
    float* ob0 = O + ((size_t)(b * L_Q + r0)     * H_N + h) * D_N;
    float* ob1 = O + ((size_t)(b * L_Q + r0 + 8) * H_N + h) * D_N;
    #pragma unroll
    for (int j = 0; j < 8; j++) {
        const int d = j * 8 + tg * 2;
        *reinterpret_cast<float2*>(ob0 + d) = make_float2(o[j][0] * inv0, o[j][1] * inv0);
        *reinterpret_cast<float2*>(ob1 + d) = make_float2(o[j][2] * inv1, o[j][3] * inv1);
    }
}

extern "C" void kernel_launch(void* const* d_in, const int* in_sizes, int n_in,
                              void* d_out, int out_size)
{
    const float* Q = (const float*)d_in[0];
    const float* K = (const float*)d_in[1];
    const float* V = (const float*)d_in[2];
    float* O = (float*)d_out;
    (void)in_sizes; (void)n_in; (void)out_size;

    void *qh, *ql, *kh, *kl, *vh, *vl;
    cudaGetSymbolAddress(&qh, g_qh);
    cudaGetSymbolAddress(&ql, g_ql);
    cudaGetSymbolAddress(&kh, g_kh);
    cudaGetSymbolAddress(&kl, g_kl);
    cudaGetSymbolAddress(&vh, g_vh);
    cudaGetSymbolAddress(&vl, g_vl);

    const int pblocks = (TOT / 4) / 256;
    const float qscale = 0.125f * 1.4426950408889634f;   // 1/sqrt(E) * log2(e)
    prep_kernel<<<pblocks, 256>>>(Q, (__nv_bfloat16*)qh, (__nv_bfloat16*)ql, qscale);
    prep_kernel<<<pblocks, 256>>>(K, (__nv_bfloat16*)kh, (__nv_bfloat16*)kl, 1.0f);
    prep_kernel<<<pblocks, 256>>>(V, (__nv_bfloat16*)vh, (__nv_bfloat16*)vl, 1.0f);

    cudaFuncSetAttribute(fullattn_hmma4_kernel,
                         cudaFuncAttributeMaxDynamicSharedMemorySize, SM_TOTAL);

    dim3 grid(L_Q / BM, B_SZ * H_N);    // 16 x 32 = 512 CTAs
    fullattn_hmma4_kernel<<<grid, NT, SM_TOTAL>>>(O);
}

// round 9
// speedup vs baseline: 1.0438x; 1.0438x over previous
#include <cuda_runtime.h>
#include <cuda_bf16.h>

// Problem constants (FullAttention_73650099192077)
#define B_SZ 4
#define L_Q  2048
#define S_K  2048
#define H_N  8
#define E_N  64
#define D_N  64

#define BM 128             // query rows per CTA (8 warps x 16)
#define BN 64              // keys per tile
#define NT 256
#define NTILES (S_K / BN)

#define TOT (B_SZ * H_N * 2048 * 64)

// Preprocessed split-bf16 tensors, layout [b*H+h][s][e] (rows of 64 bf16 = 128 B)
__device__ __nv_bfloat16 g_qh[TOT];   // Q hi (pre-scaled by 0.125*log2e)
__device__ __nv_bfloat16 g_ql[TOT];
__device__ __nv_bfloat16 g_kh[TOT];
__device__ __nv_bfloat16 g_kl[TOT];
__device__ __nv_bfloat16 g_vh[TOT];
__device__ __nv_bfloat16 g_vl[TOT];

// ---- smem: TRIPLE buffer x {KH, KL, VH, VL} of 64x64 bf16 (8 KB each) ----
#define SMB_KH 0
#define SMB_KL 8192
#define SMB_VH 16384
#define SMB_VL 24576
#define BUFSZ  32768
#define SM_TOTAL (3 * BUFSZ)    // 96 KB

// =================== helpers ===================
static __device__ __forceinline__ unsigned smem_u32(const void* p) {
    unsigned a;
    asm("{ .reg .u64 t; cvta.to.shared.u64 t, %1; cvt.u32.u64 %0, t; }" : "=r"(a) : "l"(p));
    return a;
}
static __device__ __forceinline__ unsigned swz(unsigned base, int row, int bytecol) {
    return base + (unsigned)(row * 128) + (unsigned)(bytecol ^ ((row & 7) << 4));
}
static __device__ __forceinline__ void ldsm_x4(unsigned* r, unsigned addr) {
    asm volatile("ldmatrix.sync.aligned.m8n8.x4.shared.b16 {%0,%1,%2,%3}, [%4];"
                 : "=r"(r[0]), "=r"(r[1]), "=r"(r[2]), "=r"(r[3]) : "r"(addr));
}
static __device__ __forceinline__ void ldsm_x4_t(unsigned* r, unsigned addr) {
    asm volatile("ldmatrix.sync.aligned.m8n8.x4.trans.shared.b16 {%0,%1,%2,%3}, [%4];"
                 : "=r"(r[0]), "=r"(r[1]), "=r"(r[2]), "=r"(r[3]) : "r"(addr));
}
static __device__ __forceinline__ void mma16816(float* c, const unsigned* a, unsigned b0, unsigned b1) {
    asm volatile("mma.sync.aligned.m16n8k16.row.col.f32.bf16.bf16.f32 "
                 "{%0,%1,%2,%3}, {%4,%5,%6,%7}, {%8,%9}, {%0,%1,%2,%3};"
                 : "+f"(c[0]), "+f"(c[1]), "+f"(c[2]), "+f"(c[3])
                 : "r"(a[0]), "r"(a[1]), "r"(a[2]), "r"(a[3]), "r"(b0), "r"(b1));
}
static __device__ __forceinline__ void split2(float x, float y, unsigned& h, unsigned& l) {
    __nv_bfloat162 hb = __floats2bfloat162_rn(x, y);
    float hx = __low2float(hb), hy = __high2float(hb);
    __nv_bfloat162 lb = __floats2bfloat162_rn(x - hx, y - hy);
    h = *reinterpret_cast<unsigned*>(&hb);
    l = *reinterpret_cast<unsigned*>(&lb);
}
static __device__ __forceinline__ void cpa16(unsigned saddr, const void* gp) {
    asm volatile("cp.async.cg.shared.global [%0], [%1], 16;" :: "r"(saddr), "l"(gp));
}
#define CP_COMMIT() asm volatile("cp.async.commit_group;" ::: "memory")
#define CP_WAIT(n)  asm volatile("cp.async.wait_group %0;" :: "n"(n) : "memory")

// =================== preprocess: fp32 [b,s,h,e] -> split bf16 [b*H+h][s][e] ===================
__global__ void prep_kernel(const float* __restrict__ src,
                            __nv_bfloat16* __restrict__ dh,
                            __nv_bfloat16* __restrict__ dl,
                            float scale)
{
    int idx = blockIdx.x * blockDim.x + threadIdx.x;
    int e4 = idx & 15;
    int h  = (idx >> 4) & (H_N - 1);
    int s  = (idx >> 7) & 2047;
    int b  = idx >> 18;
    float4 v = *reinterpret_cast<const float4*>(src + (size_t)idx * 4);
    unsigned h0, l0, h1, l1;
    split2(v.x * scale, v.y * scale, h0, l0);
    split2(v.z * scale, v.w * scale, h1, l1);
    size_t doff = ((((size_t)b * H_N + h) * 2048 + s) * 64 + e4 * 4);
    *reinterpret_cast<uint2*>(dh + doff) = make_uint2(h0, h1);
    *reinterpret_cast<uint2*>(dl + doff) = make_uint2(l0, l1);
}

// =================== main kernel ===================
__global__ __launch_bounds__(NT, 1)
void fullattn_hmma5_kernel(float* __restrict__ O)
{
    extern __shared__ __align__(128) char smbuf[];
    const unsigned sb = smem_u32(smbuf);

    const int t    = threadIdx.x;
    const int wid  = t >> 5;
    const int lane = t & 31;
    const int g    = lane >> 2;
    const int tg   = lane & 3;
    const int l0   = blockIdx.x * BM;
    const int bh   = blockIdx.y;
    const int b    = bh >> 3;
    const int h    = bh & 7;

    const size_t gbase = (size_t)bh * S_K * 64;

    // ---- Q (pre-scaled/split): stage 128x64 hi+lo in buf0 span, ldmatrix to A-frags ----
    {
        const int r  = t >> 1;
        const int hf = t & 1;
        const size_t qoff = ((size_t)bh * L_Q + l0 + r) * 64 + hf * 32;
        #pragma unroll
        for (int c = 0; c < 4; c++) {
            const unsigned soff = hf * 64 + c * 16;
            cpa16(swz(sb, r, soff),         g_qh + qoff + c * 8);
            cpa16(swz(sb + 16384, r, soff), g_ql + qoff + c * 8);
        }
        CP_COMMIT();
        CP_WAIT(0);
        __syncthreads();
    }
    unsigned qh[16], ql[16];
    #pragma unroll
    for (int kb = 0; kb < 4; kb++) {
        const unsigned la = swz(sb, wid * 16 + (lane & 15), kb * 32 + (lane >> 4) * 16);
        ldsm_x4(&qh[kb * 4], la);
        ldsm_x4(&ql[kb * 4], la + 16384);
    }
    __syncthreads();

    // ---- loader: each thread owns one 128B row of one array ----
    const int lrow  = t & 63;
    const int lpart = t >> 6;    // 0..3 -> KH, KL, VH, VL
    const __nv_bfloat16* lsrc =
        (lpart == 0) ? g_kh : (lpart == 1) ? g_kl : (lpart == 2) ? g_vh : g_vl;
    auto load_tile = [&](int tile, int bufsel) {
        const unsigned bb = sb + bufsel * BUFSZ + lpart * 8192;
        const size_t off = gbase + ((size_t)(tile * BN + lrow)) * 64;
        #pragma unroll
        for (int c = 0; c < 8; c++)
            cpa16(swz(bb, lrow, c * 16), lsrc + off + c * 8);
        CP_COMMIT();
    };

    auto qk_gemm = [&](unsigned bb, float (*acc)[4]) {
        #pragma unroll
        for (int j = 0; j < 8; j++)
            #pragma unroll
            for (int i = 0; i < 4; i++) acc[j][i] = 0.0f;
        #pragma unroll
        for (int jj = 0; jj < 4; jj++) {
            #pragma unroll
            for (int kb = 0; kb < 4; kb++) {
                const unsigned la = swz(bb, 16 * jj + (lane & 15), kb * 32 + (lane >> 4) * 16);
                unsigned bh4[4], bl4[4];
                ldsm_x4(bh4, la + SMB_KH);
                ldsm_x4(bl4, la + SMB_KL);
                mma16816(acc[2 * jj],     &qh[kb * 4], bh4[0], bh4[2]);
                mma16816(acc[2 * jj],     &qh[kb * 4], bl4[0], bl4[2]);
                mma16816(acc[2 * jj],     &ql[kb * 4], bh4[0], bh4[2]);
                mma16816(acc[2 * jj + 1], &qh[kb * 4], bh4[1], bh4[3]);
                mma16816(acc[2 * jj + 1], &qh[kb * 4], bl4[1], bl4[3]);
                mma16816(acc[2 * jj + 1], &ql[kb * 4], bh4[1], bh4[3]);
            }
        }
    };

    float o[8][4];
    #pragma unroll
    for (int j = 0; j < 8; j++)
        #pragma unroll
        for (int i = 0; i < 4; i++) o[j][i] = 0.0f;
    float m0 = -1e30f, m1 = -1e30f;
    float l0s = 0.0f, l1s = 0.0f;

    // ---- prologue: fill all 3 stages ----
    load_tile(0, 0);
    load_tile(1, 1);
    load_tile(2, 2);
    CP_WAIT(2);               // tile 0 complete
    __syncthreads();

    float s_a[8][4], s_b[8][4];
    qk_gemm(sb, s_a);         // tile 0 scores

    // ---- body: scores for tile t live in `cur`; compute tile t+1 scores first ----
    auto body = [&](int tile, float (*cur)[4], float (*nxt)[4]) {
        const unsigned bcur = sb + (tile % 3) * BUFSZ;

        if (tile + 1 < NTILES) {
            if (tile + 3 < NTILES) { CP_WAIT(1); }    // tile t+1 group (2 in flight)
            else                   { CP_WAIT(0); }    // tail: drain everything
            __syncthreads();
            qk_gemm(sb + ((tile + 1) % 3) * BUFSZ, nxt);
        }

        // ---- online softmax on cur (base-2) ----
        float mx0 = -1e30f, mx1 = -1e30f;
        #pragma unroll
        for (int j = 0; j < 8; j++) {
            mx0 = fmaxf(mx0, fmaxf(cur[j][0], cur[j][1]));
            mx1 = fmaxf(mx1, fmaxf(cur[j][2], cur[j][3]));
        }
        #pragma unroll
        for (int off = 1; off < 4; off <<= 1) {
            mx0 = fmaxf(mx0, __shfl_xor_sync(0xffffffffu, mx0, off));
            mx1 = fmaxf(mx1, __shfl_xor_sync(0xffffffffu, mx1, off));
        }
        const float nm0 = fmaxf(m0, mx0), nm1 = fmaxf(m1, mx1);
        const float a0 = exp2f(m0 - nm0), a1 = exp2f(m1 - nm1);
        m0 = nm0; m1 = nm1;

        float rs0 = 0.0f, rs1 = 0.0f;
        #pragma unroll
        for (int j = 0; j < 8; j++) {
            cur[j][0] = exp2f(cur[j][0] - nm0);
            cur[j][1] = exp2f(cur[j][1] - nm0);
            cur[j][2] = exp2f(cur[j][2] - nm1);
            cur[j][3] = exp2f(cur[j][3] - nm1);
            rs0 += cur[j][0] + cur[j][1];
            rs1 += cur[j][2] + cur[j][3];
        }
        #pragma unroll
        for (int off = 1; off < 4; off <<= 1) {
            rs0 += __shfl_xor_sync(0xffffffffu, rs0, off);
            rs1 += __shfl_xor_sync(0xffffffffu, rs1, off);
        }
        l0s = l0s * a0 + rs0;
        l1s = l1s * a1 + rs1;
        #pragma unroll
        for (int j = 0; j < 8; j++) {
            o[j][0] *= a0; o[j][1] *= a0;
            o[j][2] *= a1; o[j][3] *= a1;
        }

        // ---- pack P hi/lo into A-fragments ----
        unsigned ph[16], pl[16];
        #pragma unroll
        for (int kb = 0; kb < 4; kb++) {
            split2(cur[2 * kb][0],     cur[2 * kb][1],     ph[kb * 4 + 0], pl[kb * 4 + 0]);
            split2(cur[2 * kb][2],     cur[2 * kb][3],     ph[kb * 4 + 1], pl[kb * 4 + 1]);
            split2(cur[2 * kb + 1][0], cur[2 * kb + 1][1], ph[kb * 4 + 2], pl[kb * 4 + 2]);
            split2(cur[2 * kb + 1][2], cur[2 * kb + 1][3], ph[kb * 4 + 3], pl[kb * 4 + 3]);
        }

        // ---- PV on current buffer ----
        #pragma unroll
        for (int jj = 0; jj < 4; jj++) {
            #pragma unroll
            for (int kb = 0; kb < 4; kb++) {
                const unsigned la = swz(bcur, 16 * kb + (lane & 15), jj * 32 + (lane >> 4) * 16);
                unsigned vh4[4], vl4[4];
                ldsm_x4_t(vh4, la + SMB_VH);
                ldsm_x4_t(vl4, la + SMB_VL);
                mma16816(o[2 * jj],     &ph[kb * 4], vh4[0], vh4[1]);
                mma16816(o[2 * jj],     &ph[kb * 4], vl4[0], vl4[1]);
                mma16816(o[2 * jj],     &pl[kb * 4], vh4[0], vh4[1]);
                mma16816(o[2 * jj + 1], &ph[kb * 4], vh4[2], vh4[3]);
                mma16816(o[2 * jj + 1], &ph[kb * 4], vl4[2], vl4[3]);
                mma16816(o[2 * jj + 1], &pl[kb * 4], vh4[2], vh4[3]);
            }
        }

        __syncthreads();                   // buffer (tile%3) fully consumed
        if (tile + 3 < NTILES) load_tile(tile + 3, tile % 3);
    };

    #pragma unroll 1
    for (int tile = 0; tile < NTILES; tile += 2) {
        body(tile,     s_a, s_b);
        body(tile + 1, s_b, s_a);
    }

    // ---- epilogue: normalize + store ----
    const float inv0 = 1.0f / l0s;
    const float inv1 = 1.0f / l1s;
    const int r0 = l0 + wid * 16 + g;
    float* ob0 = O + ((size_t)(b * L_Q + r0)     * H_N + h) * D_N;
    float* ob1 = O + ((size_t)(b * L_Q + r0 + 8) * H_N + h) * D_N;
    #pragma unroll
    for (int j = 0; j < 8; j++) {
        const int d = j * 8 + tg * 2;
        *reinterpret_cast<float2*>(ob0 + d) = make_float2(o[j][0] * inv0, o[j][1] * inv0);
        *reinterpret_cast<float2*>(ob1 + d) = make_float2(o[j][2] * inv1, o[j][3] * inv1);
    }
}

extern "C" void kernel_launch(void* const* d_in, const int* in_sizes, int n_in,
                              void* d_out, int out_size)
{
    const float* Q = (const float*)d_in[0];
    const float* K = (const float*)d_in[1];
    const float* V = (const float*)d_in[2];
    float* O = (float*)d_out;
    (void)in_sizes; (void)n_in; (void)out_size;

    void *qh, *ql, *kh, *kl, *vh, *vl;
    cudaGetSymbolAddress(&qh, g_qh);
    cudaGetSymbolAddress(&ql, g_ql);
    cudaGetSymbolAddress(&kh, g_kh);
    cudaGetSymbolAddress(&kl, g_kl);
    cudaGetSymbolAddress(&vh, g_vh);
    cudaGetSymbolAddress(&vl, g_vl);

    const int pblocks = (TOT / 4) / 256;
    const float qscale = 0.125f * 1.4426950408889634f;   // 1/sqrt(E) * log2(e)
    prep_kernel<<<pblocks, 256>>>(Q, (__nv_bfloat16*)qh, (__nv_bfloat16*)ql, qscale);
    prep_kernel<<<pblocks, 256>>>(K, (__nv_bfloat16*)kh, (__nv_bfloat16*)kl, 1.0f);
    prep_kernel<<<pblocks, 256>>>(V, (__nv_bfloat16*)vh, (__nv_bfloat16*)vl, 1.0f);

    cudaFuncSetAttribute(fullattn_hmma5_kernel,
                         cudaFuncAttributeMaxDynamicSharedMemorySize, SM_TOTAL);

    dim3 grid(L_Q / BM, B_SZ * H_N);    // 16 x 32 = 512 CTAs
    fullattn_hmma5_kernel<<<grid, NT, SM_TOTAL>>>(O);
}